// round 4
// baseline (speedup 1.0000x reference)
#include <cuda_runtime.h>
#include <cuda_bf16.h>
#include <cstdint>

// ===================== problem dims / tiles =====================
static constexpr int T     = 4096;   // tokens (M)
static constexpr int IN_F  = 4096;   // K
static constexpr int OUT_F = 4096;   // N
static constexpr int KC    = 128;    // K chunk bytes (int8)
static constexpr int KITERS = IN_F / KC;   // 32
static constexpr int ROWB  = 144;    // smem row stride: 128B data + 16B pad (conflict-free ldmatrix)
static constexpr int STAGES = 3;
static constexpr int SSTR  = 256 * ROWB;             // bytes/stage: A rows 0-127, B rows 128-255
static constexpr int SMEM_TOTAL = STAGES * SSTR;     // 110592

// ===================== device scratch =====================
__device__ float g_partial[1024];
__device__ float g_scale;
__device__ float g_inv;
__device__ __align__(16) int8_t g_qx[(size_t)T * IN_F];     // 16MB quantized activations
__device__ __align__(16) int8_t g_wt[(size_t)OUT_F * IN_F]; // 16MB int8 weights

// ===================== helpers =====================
__device__ __forceinline__ uint32_t smem_u32(const void* p) {
    uint32_t a;
    asm("{ .reg .u64 t; cvta.to.shared.u64 t, %1; cvt.u32.u64 %0, t; }" : "=r"(a) : "l"(p));
    return a;
}
__device__ __forceinline__ void ldsm_x4(uint32_t* r, uint32_t addr) {
    asm volatile("ldmatrix.sync.aligned.m8n8.x4.shared.b16 {%0,%1,%2,%3}, [%4];"
                 : "=r"(r[0]), "=r"(r[1]), "=r"(r[2]), "=r"(r[3]) : "r"(addr));
}
__device__ __forceinline__ void mma_s8(int* c, const uint32_t* a, const uint32_t* b) {
    asm volatile(
        "mma.sync.aligned.m16n8k32.row.col.s32.s8.s8.s32 "
        "{%0,%1,%2,%3}, {%4,%5,%6,%7}, {%8,%9}, {%0,%1,%2,%3};"
        : "+r"(c[0]), "+r"(c[1]), "+r"(c[2]), "+r"(c[3])
        : "r"(a[0]), "r"(a[1]), "r"(a[2]), "r"(a[3]), "r"(b[0]), "r"(b[1]));
}
__device__ __forceinline__ void cp16(uint32_t saddr, const void* gaddr) {
    asm volatile("cp.async.cg.shared.global [%0], [%1], 16;" :: "r"(saddr), "l"(gaddr));
}
__device__ __forceinline__ void cp_commit() {
    asm volatile("cp.async.commit_group;" ::: "memory");
}
__device__ __forceinline__ void cp_wait1() {
    asm volatile("cp.async.wait_group 1;" ::: "memory");
}

// ===================== stage 1: max|x| =====================
__global__ void k_maxabs(const float* __restrict__ x) {
    __shared__ float red[256];
    float m = 0.f;
    const float4* x4 = (const float4*)x;
    const int n4 = T * IN_F / 4;
    for (int i = blockIdx.x * blockDim.x + threadIdx.x; i < n4; i += gridDim.x * blockDim.x) {
        float4 v = x4[i];
        m = fmaxf(m, fmaxf(fmaxf(fabsf(v.x), fabsf(v.y)), fmaxf(fabsf(v.z), fabsf(v.w))));
    }
    red[threadIdx.x] = m;
    __syncthreads();
    #pragma unroll
    for (int s = 128; s > 0; s >>= 1) {
        if (threadIdx.x < s) red[threadIdx.x] = fmaxf(red[threadIdx.x], red[threadIdx.x + s]);
        __syncthreads();
    }
    if (threadIdx.x == 0) g_partial[blockIdx.x] = red[0];
}

__global__ void k_finalize() {
    __shared__ float red[1024];
    red[threadIdx.x] = g_partial[threadIdx.x];
    __syncthreads();
    #pragma unroll
    for (int s = 512; s > 0; s >>= 1) {
        if (threadIdx.x < s) red[threadIdx.x] = fmaxf(red[threadIdx.x], red[threadIdx.x + s]);
        __syncthreads();
    }
    if (threadIdx.x == 0) {
        float sc = __fdiv_rn(red[0], 127.0f);
        g_scale = sc;
        g_inv = __fdiv_rn(1.0f, sc);
    }
}

// ===================== stage 2: fused quantize-x + weight-convert =====================
__global__ void k_prep(const float* __restrict__ x, const int* __restrict__ w) {
    const int HALF = 1024;
    const int n4 = T * IN_F / 4;
    if (blockIdx.x < HALF) {
        const float inv = g_inv;
        const float4* x4 = (const float4*)x;
        uint32_t* o = (uint32_t*)g_qx;
        for (int i = blockIdx.x * blockDim.x + threadIdx.x; i < n4; i += HALF * blockDim.x) {
            float4 v = x4[i];
            // |x*inv| <= 127*(1+eps): round-to-nearest lands in [-127,127], no clamp.
            int q0 = __float2int_rn(v.x * inv);
            int q1 = __float2int_rn(v.y * inv);
            int q2 = __float2int_rn(v.z * inv);
            int q3 = __float2int_rn(v.w * inv);
            o[i] = (q0 & 0xFF) | ((q1 & 0xFF) << 8) | ((q2 & 0xFF) << 16) | ((uint32_t)(q3 & 0xFF) << 24);
        }
    } else {
        const int4* w4 = (const int4*)w;
        uint32_t* o = (uint32_t*)g_wt;
        for (int i = (blockIdx.x - HALF) * blockDim.x + threadIdx.x; i < n4; i += HALF * blockDim.x) {
            int4 v = w4[i];
            o[i] = (v.x & 0xFF) | ((v.y & 0xFF) << 8) | ((v.z & 0xFF) << 16) | ((uint32_t)(v.w & 0xFF) << 24);
        }
    }
}

// ===================== stage 3: int8 mma.sync GEMM, 3-stage cp.async, KC=128 =====================
// CTA 128x128, 8 warps in 2(M) x 4(N), warp tile 64x32, 2 CTAs/SM.
__global__ void __launch_bounds__(256, 2) k_gemm(const float* __restrict__ wscale,
                                                 const float* __restrict__ bias,
                                                 float* __restrict__ out) {
    extern __shared__ __align__(16) char smem[];
    const uint32_t sbase = smem_u32(smem);

    const int tid  = threadIdx.x;
    const int lane = tid & 31;
    const int wid  = tid >> 5;
    const int mwarp = wid >> 2;     // 0..1
    const int nwarp = wid & 3;      // 0..3
    const int Mbase = blockIdx.y * 128;
    const int Nbase = blockIdx.x * 128;

    // staging: thread tid owns one full 128B row: rows 0-127 = A, 128-255 = B
    const int srow = tid;                // 0..255
    const int8_t* grow = (srow < 128)
        ? (g_qx + (size_t)(Mbase + srow) * IN_F)
        : (g_wt + (size_t)(Nbase + (srow - 128)) * IN_F);
    const uint32_t srowoff = sbase + (uint32_t)srow * ROWB;

    // ldmatrix per-thread offsets (relative to stage base)
    const int tile = lane >> 3;
    const int sub  = lane & 7;
    uint32_t aoff[4], boff[2];
    #pragma unroll
    for (int mb = 0; mb < 4; ++mb)
        aoff[mb] = sbase + (uint32_t)(mwarp * 64 + mb * 16 + (tile & 1) * 8 + sub) * ROWB
                 + (uint32_t)(tile >> 1) * 16;
    #pragma unroll
    for (int p = 0; p < 2; ++p)
        boff[p] = sbase + (uint32_t)(128 + nwarp * 32 + p * 16 + (tile >> 1) * 8 + sub) * ROWB
                 + (uint32_t)(tile & 1) * 16;

    int acc[4][4][4];
    #pragma unroll
    for (int mb = 0; mb < 4; ++mb)
        #pragma unroll
        for (int nb = 0; nb < 4; ++nb)
            #pragma unroll
            for (int f = 0; f < 4; ++f) acc[mb][nb][f] = 0;

    // prologue: issue stages 0,1
    #pragma unroll
    for (int s = 0; s < 2; ++s) {
        const uint32_t so = (uint32_t)s * SSTR;
        #pragma unroll
        for (int j = 0; j < 8; ++j)
            cp16(srowoff + so + j * 16, grow + s * KC + j * 16);
        cp_commit();
    }

    for (int it = 0; it < KITERS; ++it) {
        cp_wait1();                 // stage it landed (newest group may be outstanding)
        __syncthreads();            // visible to all; all warps done reading stage it-1

        // issue stage it+2 into slot (it+2)%3 (freed: its old contents were read in iter it-1)
        if (it + 2 < KITERS) {
            const uint32_t so = (uint32_t)((it + 2) % 3) * SSTR;
            const int ko = (it + 2) * KC;
            #pragma unroll
            for (int j = 0; j < 8; ++j)
                cp16(srowoff + so + j * 16, grow + ko + j * 16);
        }
        cp_commit();                // uniform group count even at tail

        const uint32_t so = (uint32_t)(it % 3) * SSTR;
        #pragma unroll
        for (int ks = 0; ks < 4; ++ks) {
            uint32_t af[4][4];
            uint32_t bf[4][2];
            #pragma unroll
            for (int mb = 0; mb < 4; ++mb)
                ldsm_x4(af[mb], aoff[mb] + so + ks * 32);
            #pragma unroll
            for (int p = 0; p < 2; ++p) {
                uint32_t r[4];
                ldsm_x4(r, boff[p] + so + ks * 32);
                bf[p * 2 + 0][0] = r[0]; bf[p * 2 + 0][1] = r[1];
                bf[p * 2 + 1][0] = r[2]; bf[p * 2 + 1][1] = r[3];
            }
            #pragma unroll
            for (int mb = 0; mb < 4; ++mb)
                #pragma unroll
                for (int nb = 0; nb < 4; ++nb)
                    mma_s8(acc[mb][nb], af[mb], bf[nb]);
        }
    }

    // epilogue: exact int32 -> fp32 scale + bias
    const float s = g_scale * wscale[0];
    const int g   = lane >> 2;
    const int tg2 = (lane & 3) * 2;
    #pragma unroll
    for (int nb = 0; nb < 4; ++nb) {
        const int col = Nbase + nwarp * 32 + nb * 8 + tg2;
        const float2 bb = *(const float2*)(bias + col);
        #pragma unroll
        for (int mb = 0; mb < 4; ++mb) {
            const int row = Mbase + mwarp * 64 + mb * 16 + g;
            float2 v0, v1;
            v0.x = fmaf((float)acc[mb][nb][0], s, bb.x);
            v0.y = fmaf((float)acc[mb][nb][1], s, bb.y);
            v1.x = fmaf((float)acc[mb][nb][2], s, bb.x);
            v1.y = fmaf((float)acc[mb][nb][3], s, bb.y);
            *(float2*)(out + (size_t)row * OUT_F + col)       = v0;
            *(float2*)(out + (size_t)(row + 8) * OUT_F + col) = v1;
        }
    }
}

// ===================== launch =====================
extern "C" void kernel_launch(void* const* d_in, const int* in_sizes, int n_in,
                              void* d_out, int out_size) {
    const float* x    = (const float*)d_in[0];
    const int*   qw   = (const int*)d_in[1];
    const float* ws   = (const float*)d_in[2];
    const float* bias = (const float*)d_in[3];
    float* out = (float*)d_out;

    k_maxabs<<<1024, 256>>>(x);
    k_finalize<<<1, 1024>>>();
    k_prep<<<2048, 256>>>(x, qw);
    cudaFuncSetAttribute(k_gemm, cudaFuncAttributeMaxDynamicSharedMemorySize, SMEM_TOTAL);
    k_gemm<<<dim3(OUT_F / 128, T / 128), 256, SMEM_TOTAL>>>(ws, bias, out);
}

// round 5
// speedup vs baseline: 1.1232x; 1.1232x over previous
#include <cuda_runtime.h>
#include <cuda_bf16.h>
#include <cstdint>

// ===================== problem dims / tiles =====================
static constexpr int T     = 4096;   // tokens (M)
static constexpr int IN_F  = 4096;   // K
static constexpr int OUT_F = 4096;   // N
static constexpr int KC    = 64;     // K chunk bytes (int8)
static constexpr int KITERS = IN_F / KC;   // 64
static constexpr int ROWB  = 80;     // smem row stride (conflict-free ldmatrix)
static constexpr int STAGES = 4;
static constexpr int SSTR  = 256 * ROWB;             // bytes per stage (A rows 0-127, B rows 128-255)
static constexpr int SMEM_TOTAL = STAGES * SSTR;     // 81920

// ===================== device scratch =====================
__device__ unsigned int g_absmax_bits;               // fabs(x) max as uint bits (order-independent)
__device__ __align__(16) int8_t g_qx[(size_t)T * IN_F];     // 16MB quantized activations
__device__ __align__(16) int8_t g_wt[(size_t)OUT_F * IN_F]; // 16MB int8 weights

// ===================== helpers =====================
__device__ __forceinline__ uint32_t smem_u32(const void* p) {
    uint32_t a;
    asm("{ .reg .u64 t; cvta.to.shared.u64 t, %1; cvt.u32.u64 %0, t; }" : "=r"(a) : "l"(p));
    return a;
}
__device__ __forceinline__ void ldsm_x4(uint32_t* r, uint32_t addr) {
    asm volatile("ldmatrix.sync.aligned.m8n8.x4.shared.b16 {%0,%1,%2,%3}, [%4];"
                 : "=r"(r[0]), "=r"(r[1]), "=r"(r[2]), "=r"(r[3]) : "r"(addr));
}
__device__ __forceinline__ void mma_s8(int* c, const uint32_t* a, const uint32_t* b) {
    asm volatile(
        "mma.sync.aligned.m16n8k32.row.col.s32.s8.s8.s32 "
        "{%0,%1,%2,%3}, {%4,%5,%6,%7}, {%8,%9}, {%0,%1,%2,%3};"
        : "+r"(c[0]), "+r"(c[1]), "+r"(c[2]), "+r"(c[3])
        : "r"(a[0]), "r"(a[1]), "r"(a[2]), "r"(a[3]), "r"(b[0]), "r"(b[1]));
}
__device__ __forceinline__ void cp16(uint32_t saddr, const void* gaddr) {
    asm volatile("cp.async.cg.shared.global [%0], [%1], 16;" :: "r"(saddr), "l"(gaddr));
}
__device__ __forceinline__ void cp_commit() {
    asm volatile("cp.async.commit_group;" ::: "memory");
}
__device__ __forceinline__ void cp_wait2() {
    asm volatile("cp.async.wait_group 2;" ::: "memory");
}

// ===================== stage 0: reset reduction cell (graph replays need this) =====================
__global__ void k_reset() { g_absmax_bits = 0u; }

// ===================== stage 1: fused max|x| scan + weight int32->int8 =====================
// blocks [0,1024): scan x, atomicMax the |x| bits. blocks [1024,2048): convert w.
// fabs(x) >= 0 so float bit pattern is monotonic -> uint max == float max. Deterministic.
__global__ void k_scan_wconv(const float* __restrict__ x, const int* __restrict__ w) {
    const int HALF = 1024;
    const int n4 = T * IN_F / 4;
    if (blockIdx.x < HALF) {
        __shared__ float red[256];
        float m = 0.f;
        const float4* x4 = (const float4*)x;
        for (int i = blockIdx.x * blockDim.x + threadIdx.x; i < n4; i += HALF * blockDim.x) {
            float4 v = x4[i];
            m = fmaxf(m, fmaxf(fmaxf(fabsf(v.x), fabsf(v.y)), fmaxf(fabsf(v.z), fabsf(v.w))));
        }
        red[threadIdx.x] = m;
        __syncthreads();
        #pragma unroll
        for (int s = 128; s > 0; s >>= 1) {
            if (threadIdx.x < s) red[threadIdx.x] = fmaxf(red[threadIdx.x], red[threadIdx.x + s]);
            __syncthreads();
        }
        if (threadIdx.x == 0) atomicMax(&g_absmax_bits, __float_as_uint(red[0]));
    } else {
        const int4* w4 = (const int4*)w;
        uint32_t* o = (uint32_t*)g_wt;
        for (int i = (blockIdx.x - HALF) * blockDim.x + threadIdx.x; i < n4; i += HALF * blockDim.x) {
            int4 v = w4[i];
            o[i] = (v.x & 0xFF) | ((v.y & 0xFF) << 8) | ((v.z & 0xFF) << 16) | ((uint32_t)(v.w & 0xFF) << 24);
        }
    }
}

// ===================== stage 2: quantize x -> int8 =====================
__global__ void k_quant(const float* __restrict__ x) {
    __shared__ float s_inv;
    if (threadIdx.x == 0) {
        float absmax = __uint_as_float(g_absmax_bits);
        float sc = __fdiv_rn(absmax, 127.0f);
        s_inv = __fdiv_rn(1.0f, sc);
    }
    __syncthreads();
    const float inv = s_inv;
    const float4* x4 = (const float4*)x;
    uint32_t* o = (uint32_t*)g_qx;
    const int n4 = T * IN_F / 4;
    for (int i = blockIdx.x * blockDim.x + threadIdx.x; i < n4; i += gridDim.x * blockDim.x) {
        float4 v = x4[i];
        // |x*inv| <= 127*(1+eps): round-to-nearest lands in [-127,127], no clamp.
        int q0 = __float2int_rn(v.x * inv);
        int q1 = __float2int_rn(v.y * inv);
        int q2 = __float2int_rn(v.z * inv);
        int q3 = __float2int_rn(v.w * inv);
        o[i] = (q0 & 0xFF) | ((q1 & 0xFF) << 8) | ((q2 & 0xFF) << 16) | ((uint32_t)(q3 & 0xFF) << 24);
    }
}

// ===================== stage 3: int8 mma.sync GEMM, 4-stage cp.async (R3-verified) =====================
// CTA 128x128, 8 warps in 2(M) x 4(N), warp tile 64x32, 2 CTAs/SM.
__global__ void __launch_bounds__(256, 2) k_gemm(const float* __restrict__ wscale,
                                                 const float* __restrict__ bias,
                                                 float* __restrict__ out) {
    extern __shared__ __align__(16) char smem[];
    const uint32_t sbase = smem_u32(smem);

    const int tid  = threadIdx.x;
    const int lane = tid & 31;
    const int wid  = tid >> 5;
    const int mwarp = wid >> 2;     // 0..1
    const int nwarp = wid & 3;      // 0..3
    const int Mbase = blockIdx.y * 128;
    const int Nbase = blockIdx.x * 128;

    // per-thread staging: A rows r0, r0+64 -> smem rows r0, r0+64
    //                     B rows r0, r0+64 -> smem rows 128+r0, 192+r0
    const int r0 = tid >> 2;             // 0..63
    const int cb = (tid & 3) * 16;       // byte col in 64B chunk
    const int8_t* gA0 = g_qx + (size_t)(Mbase + r0)      * IN_F + cb;
    const int8_t* gA1 = g_qx + (size_t)(Mbase + r0 + 64) * IN_F + cb;
    const int8_t* gB0 = g_wt + (size_t)(Nbase + r0)      * IN_F + cb;
    const int8_t* gB1 = g_wt + (size_t)(Nbase + r0 + 64) * IN_F + cb;
    const uint32_t sA0 = sbase + (uint32_t)r0 * ROWB + cb;
    const uint32_t sA1 = sA0 + 64u * ROWB;
    const uint32_t sB0 = sA0 + 128u * ROWB;
    const uint32_t sB1 = sA0 + 192u * ROWB;

    // ldmatrix per-thread offsets (relative to stage base)
    const int tile = lane >> 3;
    const int sub  = lane & 7;
    uint32_t aoff[4], boff[2];
    #pragma unroll
    for (int mb = 0; mb < 4; ++mb)
        aoff[mb] = sbase + (uint32_t)(mwarp * 64 + mb * 16 + (tile & 1) * 8 + sub) * ROWB
                 + (uint32_t)(tile >> 1) * 16;
    #pragma unroll
    for (int p = 0; p < 2; ++p)
        boff[p] = sbase + (uint32_t)(128 + nwarp * 32 + p * 16 + (tile >> 1) * 8 + sub) * ROWB
                 + (uint32_t)(tile & 1) * 16;

    int acc[4][4][4];
    #pragma unroll
    for (int mb = 0; mb < 4; ++mb)
        #pragma unroll
        for (int nb = 0; nb < 4; ++nb)
            #pragma unroll
            for (int f = 0; f < 4; ++f) acc[mb][nb][f] = 0;

    // prologue: issue stages 0..2
    #pragma unroll
    for (int s = 0; s < STAGES - 1; ++s) {
        const uint32_t so = (uint32_t)s * SSTR;
        const int ko = s * KC;
        cp16(sA0 + so, gA0 + ko);
        cp16(sA1 + so, gA1 + ko);
        cp16(sB0 + so, gB0 + ko);
        cp16(sB1 + so, gB1 + ko);
        cp_commit();
    }

    for (int it = 0; it < KITERS; ++it) {
        cp_wait2();                 // stage it landed
        __syncthreads();            // visible to all; all warps done with stage it-1

        // issue stage it+3 (overwrites slot of stage it-1, safe after the barrier)
        if (it + STAGES - 1 < KITERS) {
            const uint32_t so = (uint32_t)((it + STAGES - 1) & (STAGES - 1)) * SSTR;
            const int ko = (it + STAGES - 1) * KC;
            cp16(sA0 + so, gA0 + ko);
            cp16(sA1 + so, gA1 + ko);
            cp16(sB0 + so, gB0 + ko);
            cp16(sB1 + so, gB1 + ko);
        }
        cp_commit();                // commit every iter (empty at tail) to keep group counts uniform

        const uint32_t so = (uint32_t)(it & (STAGES - 1)) * SSTR;
        #pragma unroll
        for (int ks = 0; ks < 2; ++ks) {
            uint32_t af[4][4];
            uint32_t bf[4][2];
            #pragma unroll
            for (int mb = 0; mb < 4; ++mb)
                ldsm_x4(af[mb], aoff[mb] + so + ks * 32);
            #pragma unroll
            for (int p = 0; p < 2; ++p) {
                uint32_t r[4];
                ldsm_x4(r, boff[p] + so + ks * 32);
                bf[p * 2 + 0][0] = r[0]; bf[p * 2 + 0][1] = r[1];
                bf[p * 2 + 1][0] = r[2]; bf[p * 2 + 1][1] = r[3];
            }
            #pragma unroll
            for (int mb = 0; mb < 4; ++mb)
                #pragma unroll
                for (int nb = 0; nb < 4; ++nb)
                    mma_s8(acc[mb][nb], af[mb], bf[nb]);
        }
    }

    // epilogue: exact int32 -> fp32 scale + bias
    const float s = __fdiv_rn(__uint_as_float(g_absmax_bits), 127.0f) * wscale[0];
    const int g   = lane >> 2;
    const int tg2 = (lane & 3) * 2;
    #pragma unroll
    for (int nb = 0; nb < 4; ++nb) {
        const int col = Nbase + nwarp * 32 + nb * 8 + tg2;
        const float2 bb = *(const float2*)(bias + col);
        #pragma unroll
        for (int mb = 0; mb < 4; ++mb) {
            const int row = Mbase + mwarp * 64 + mb * 16 + g;
            float2 v0, v1;
            v0.x = fmaf((float)acc[mb][nb][0], s, bb.x);
            v0.y = fmaf((float)acc[mb][nb][1], s, bb.y);
            v1.x = fmaf((float)acc[mb][nb][2], s, bb.x);
            v1.y = fmaf((float)acc[mb][nb][3], s, bb.y);
            *(float2*)(out + (size_t)row * OUT_F + col)       = v0;
            *(float2*)(out + (size_t)(row + 8) * OUT_F + col) = v1;
        }
    }
}

// ===================== launch =====================
extern "C" void kernel_launch(void* const* d_in, const int* in_sizes, int n_in,
                              void* d_out, int out_size) {
    const float* x    = (const float*)d_in[0];
    const int*   qw   = (const int*)d_in[1];
    const float* ws   = (const float*)d_in[2];
    const float* bias = (const float*)d_in[3];
    float* out = (float*)d_out;

    k_reset<<<1, 1>>>();
    k_scan_wconv<<<2048, 256>>>(x, qw);
    k_quant<<<1024, 256>>>(x);
    cudaFuncSetAttribute(k_gemm, cudaFuncAttributeMaxDynamicSharedMemorySize, SMEM_TOTAL);
    k_gemm<<<dim3(OUT_F / 128, T / 128), 256, SMEM_TOTAL>>>(ws, bias, out);
}

// round 6
// speedup vs baseline: 1.1436x; 1.0182x over previous
#include <cuda_runtime.h>
#include <cuda_bf16.h>
#include <cstdint>

// ===================== problem dims / tiles =====================
static constexpr int T     = 4096;   // tokens (M)
static constexpr int IN_F  = 4096;   // K
static constexpr int OUT_F = 4096;   // N
static constexpr int KC    = 64;     // K chunk bytes (int8)
static constexpr int KITERS = IN_F / KC;   // 64
static constexpr int ROWB  = 80;     // smem row stride (conflict-free ldmatrix AND dp4a lds)
static constexpr int STAGES = 4;
static constexpr int SSTR  = 256 * ROWB;             // bytes per stage (A rows 0-127, B rows 128-255)
static constexpr int SMEM_TOTAL = STAGES * SSTR;     // 81920

// ===================== device scratch =====================
__device__ float g_partial[1024];
__device__ float g_scale;
__device__ float g_inv;
__device__ __align__(16) int8_t g_qx[(size_t)T * IN_F];     // 16MB quantized activations
__device__ __align__(16) int8_t g_wt[(size_t)OUT_F * IN_F]; // 16MB int8 weights

// ===================== helpers =====================
__device__ __forceinline__ uint32_t smem_u32(const void* p) {
    uint32_t a;
    asm("{ .reg .u64 t; cvta.to.shared.u64 t, %1; cvt.u32.u64 %0, t; }" : "=r"(a) : "l"(p));
    return a;
}
__device__ __forceinline__ void ldsm_x4(uint32_t* r, uint32_t addr) {
    asm volatile("ldmatrix.sync.aligned.m8n8.x4.shared.b16 {%0,%1,%2,%3}, [%4];"
                 : "=r"(r[0]), "=r"(r[1]), "=r"(r[2]), "=r"(r[3]) : "r"(addr));
}
__device__ __forceinline__ void mma_s8(int* c, const uint32_t* a, const uint32_t* b) {
    asm volatile(
        "mma.sync.aligned.m16n8k32.row.col.s32.s8.s8.s32 "
        "{%0,%1,%2,%3}, {%4,%5,%6,%7}, {%8,%9}, {%0,%1,%2,%3};"
        : "+r"(c[0]), "+r"(c[1]), "+r"(c[2]), "+r"(c[3])
        : "r"(a[0]), "r"(a[1]), "r"(a[2]), "r"(a[3]), "r"(b[0]), "r"(b[1]));
}
__device__ __forceinline__ int lds32(uint32_t addr) {
    int v;
    asm volatile("ld.shared.b32 %0, [%1];" : "=r"(v) : "r"(addr));
    return v;
}
__device__ __forceinline__ void cp16(uint32_t saddr, const void* gaddr) {
    asm volatile("cp.async.cg.shared.global [%0], [%1], 16;" :: "r"(saddr), "l"(gaddr));
}
__device__ __forceinline__ void cp_commit() {
    asm volatile("cp.async.commit_group;" ::: "memory");
}
__device__ __forceinline__ void cp_wait2() {
    asm volatile("cp.async.wait_group 2;" ::: "memory");
}

// ===================== stage 1: max|x| =====================
__global__ void k_maxabs(const float* __restrict__ x) {
    __shared__ float red[256];
    float m = 0.f;
    const float4* x4 = (const float4*)x;
    const int n4 = T * IN_F / 4;
    for (int i = blockIdx.x * blockDim.x + threadIdx.x; i < n4; i += gridDim.x * blockDim.x) {
        float4 v = x4[i];
        m = fmaxf(m, fmaxf(fmaxf(fabsf(v.x), fabsf(v.y)), fmaxf(fabsf(v.z), fabsf(v.w))));
    }
    red[threadIdx.x] = m;
    __syncthreads();
    #pragma unroll
    for (int s = 128; s > 0; s >>= 1) {
        if (threadIdx.x < s) red[threadIdx.x] = fmaxf(red[threadIdx.x], red[threadIdx.x + s]);
        __syncthreads();
    }
    if (threadIdx.x == 0) g_partial[blockIdx.x] = red[0];
}

__global__ void k_finalize() {
    __shared__ float red[1024];
    red[threadIdx.x] = g_partial[threadIdx.x];
    __syncthreads();
    #pragma unroll
    for (int s = 512; s > 0; s >>= 1) {
        if (threadIdx.x < s) red[threadIdx.x] = fmaxf(red[threadIdx.x], red[threadIdx.x + s]);
        __syncthreads();
    }
    if (threadIdx.x == 0) {
        float sc = __fdiv_rn(red[0], 127.0f);
        g_scale = sc;
        g_inv = __fdiv_rn(1.0f, sc);
    }
}

// ===================== stage 2: fused quantize-x + weight-convert =====================
__global__ void k_prep(const float* __restrict__ x, const int* __restrict__ w) {
    const int HALF = 1024;
    const int n4 = T * IN_F / 4;
    if (blockIdx.x < HALF) {
        const float inv = g_inv;
        const float4* x4 = (const float4*)x;
        uint32_t* o = (uint32_t*)g_qx;
        for (int i = blockIdx.x * blockDim.x + threadIdx.x; i < n4; i += HALF * blockDim.x) {
            float4 v = x4[i];
            // |x*inv| <= 127*(1+eps): round-to-nearest lands in [-127,127], no clamp.
            int q0 = __float2int_rn(v.x * inv);
            int q1 = __float2int_rn(v.y * inv);
            int q2 = __float2int_rn(v.z * inv);
            int q3 = __float2int_rn(v.w * inv);
            o[i] = (q0 & 0xFF) | ((q1 & 0xFF) << 8) | ((q2 & 0xFF) << 16) | ((uint32_t)(q3 & 0xFF) << 24);
        }
    } else {
        const int4* w4 = (const int4*)w;
        uint32_t* o = (uint32_t*)g_wt;
        for (int i = (blockIdx.x - HALF) * blockDim.x + threadIdx.x; i < n4; i += HALF * blockDim.x) {
            int4 v = w4[i];
            o[i] = (v.x & 0xFF) | ((v.y & 0xFF) << 8) | ((v.z & 0xFF) << 16) | ((uint32_t)(v.w & 0xFF) << 24);
        }
    }
}

// ===================== stage 3: hybrid tensor+dp4a GEMM =====================
// CTA 128x128, 2 CTAs/SM. Warps 0-3: mma.sync on N[0,64) (one per SMSP).
// Warps 4-7: dp4a 8x8 register tile on N[64,128) (one per SMSP).
// Both pipes run concurrently on every SMSP.
__global__ void __launch_bounds__(256, 2) k_gemm(const float* __restrict__ wscale,
                                                 const float* __restrict__ bias,
                                                 float* __restrict__ out) {
    extern __shared__ __align__(16) char smem[];
    const uint32_t sbase = smem_u32(smem);

    const int tid  = threadIdx.x;
    const int lane = tid & 31;
    const int wid  = tid >> 5;
    const int Mbase = blockIdx.y * 128;
    const int Nbase = blockIdx.x * 128;

    // ---- staging (all 256 threads): A rows r0, r0+64; B rows 128+r0, 192+r0 ----
    const int r0 = tid >> 2;             // 0..63
    const int cb = (tid & 3) * 16;       // byte col in 64B chunk
    const int8_t* gA0 = g_qx + (size_t)(Mbase + r0)      * IN_F + cb;
    const int8_t* gA1 = g_qx + (size_t)(Mbase + r0 + 64) * IN_F + cb;
    const int8_t* gB0 = g_wt + (size_t)(Nbase + r0)      * IN_F + cb;
    const int8_t* gB1 = g_wt + (size_t)(Nbase + r0 + 64) * IN_F + cb;
    const uint32_t sA0 = sbase + (uint32_t)r0 * ROWB + cb;
    const uint32_t sA1 = sA0 + 64u * ROWB;
    const uint32_t sB0 = sA0 + 128u * ROWB;
    const uint32_t sB1 = sA0 + 192u * ROWB;

    // ---- tensor warps (wid 0-3): 2(M) x 2(N), warp tile 64x32, cols [0,64) ----
    const int mwarp = wid >> 1;          // 0..1 (valid for wid<4)
    const int nwarp = wid & 1;           // 0..1
    const int tile = lane >> 3;
    const int sub  = lane & 7;
    uint32_t aoff[4], boff[2];
    #pragma unroll
    for (int mb = 0; mb < 4; ++mb)
        aoff[mb] = sbase + (uint32_t)(mwarp * 64 + mb * 16 + (tile & 1) * 8 + sub) * ROWB
                 + (uint32_t)(tile >> 1) * 16;
    #pragma unroll
    for (int p = 0; p < 2; ++p)
        boff[p] = sbase + (uint32_t)(128 + nwarp * 32 + p * 16 + (tile >> 1) * 8 + sub) * ROWB
                 + (uint32_t)(tile & 1) * 16;

    // ---- dp4a warps (wid 4-7): 2(M) x 2(N), warp tile 64x32, cols [64,128) ----
    const int dw   = wid - 4;            // 0..3 (valid for wid>=4)
    const int wrow = (dw >> 1) * 64;     // 0 or 64
    const int wcol = 64 + (dw & 1) * 32; // 64 or 96
    const int trow = lane >> 2;          // 0..7  -> rows wrow+trow+8i
    const int tcol = lane & 3;           // 0..3  -> cols wcol+tcol+4j
    const uint32_t dA = sbase + (uint32_t)(wrow + trow) * ROWB;        // +i*8*ROWB
    const uint32_t dB = sbase + (uint32_t)(128 + wcol + tcol) * ROWB;  // +j*4*ROWB

    int acc[4][4][4];                    // tensor accumulators
    #pragma unroll
    for (int mb = 0; mb < 4; ++mb)
        #pragma unroll
        for (int nb = 0; nb < 4; ++nb)
            #pragma unroll
            for (int f = 0; f < 4; ++f) acc[mb][nb][f] = 0;
    int dacc[8][8];                      // dp4a accumulators
    #pragma unroll
    for (int i = 0; i < 8; ++i)
        #pragma unroll
        for (int j = 0; j < 8; ++j) dacc[i][j] = 0;

    // prologue: issue stages 0..2
    #pragma unroll
    for (int s = 0; s < STAGES - 1; ++s) {
        const uint32_t so = (uint32_t)s * SSTR;
        const int ko = s * KC;
        cp16(sA0 + so, gA0 + ko);
        cp16(sA1 + so, gA1 + ko);
        cp16(sB0 + so, gB0 + ko);
        cp16(sB1 + so, gB1 + ko);
        cp_commit();
    }

    for (int it = 0; it < KITERS; ++it) {
        cp_wait2();                 // stage it landed
        __syncthreads();            // all warps done with stage it-1

        if (it + STAGES - 1 < KITERS) {
            const uint32_t so = (uint32_t)((it + STAGES - 1) & (STAGES - 1)) * SSTR;
            const int ko = (it + STAGES - 1) * KC;
            cp16(sA0 + so, gA0 + ko);
            cp16(sA1 + so, gA1 + ko);
            cp16(sB0 + so, gB0 + ko);
            cp16(sB1 + so, gB1 + ko);
        }
        cp_commit();

        const uint32_t so = (uint32_t)(it & (STAGES - 1)) * SSTR;

        if (wid < 4) {
            // ---------- tensor path ----------
            #pragma unroll
            for (int ks = 0; ks < 2; ++ks) {
                uint32_t af[4][4];
                uint32_t bf[4][2];
                #pragma unroll
                for (int mb = 0; mb < 4; ++mb)
                    ldsm_x4(af[mb], aoff[mb] + so + ks * 32);
                #pragma unroll
                for (int p = 0; p < 2; ++p) {
                    uint32_t r[4];
                    ldsm_x4(r, boff[p] + so + ks * 32);
                    bf[p * 2 + 0][0] = r[0]; bf[p * 2 + 0][1] = r[1];
                    bf[p * 2 + 1][0] = r[2]; bf[p * 2 + 1][1] = r[3];
                }
                #pragma unroll
                for (int mb = 0; mb < 4; ++mb)
                    #pragma unroll
                    for (int nb = 0; nb < 4; ++nb)
                        mma_s8(acc[mb][nb], af[mb], bf[nb]);
            }
        } else {
            // ---------- dp4a path ----------
            #pragma unroll 4
            for (int q = 0; q < 16; ++q) {   // 16 x 4-byte K-words per 64B chunk
                int a[8], b[8];
                #pragma unroll
                for (int i = 0; i < 8; ++i)
                    a[i] = lds32(dA + so + (uint32_t)i * (8u * ROWB) + (uint32_t)q * 4u);
                #pragma unroll
                for (int j = 0; j < 8; ++j)
                    b[j] = lds32(dB + so + (uint32_t)j * (4u * ROWB) + (uint32_t)q * 4u);
                #pragma unroll
                for (int i = 0; i < 8; ++i)
                    #pragma unroll
                    for (int j = 0; j < 8; ++j)
                        dacc[i][j] = __dp4a(a[i], b[j], dacc[i][j]);
            }
        }
    }

    // ---------- epilogue: exact int32 -> fp32 scale + bias ----------
    const float s = g_scale * wscale[0];
    if (wid < 4) {
        const int g   = lane >> 2;
        const int tg2 = (lane & 3) * 2;
        #pragma unroll
        for (int nb = 0; nb < 4; ++nb) {
            const int col = Nbase + nwarp * 32 + nb * 8 + tg2;
            const float2 bb = *(const float2*)(bias + col);
            #pragma unroll
            for (int mb = 0; mb < 4; ++mb) {
                const int row = Mbase + mwarp * 64 + mb * 16 + g;
                float2 v0, v1;
                v0.x = fmaf((float)acc[mb][nb][0], s, bb.x);
                v0.y = fmaf((float)acc[mb][nb][1], s, bb.y);
                v1.x = fmaf((float)acc[mb][nb][2], s, bb.x);
                v1.y = fmaf((float)acc[mb][nb][3], s, bb.y);
                *(float2*)(out + (size_t)row * OUT_F + col)       = v0;
                *(float2*)(out + (size_t)(row + 8) * OUT_F + col) = v1;
            }
        }
    } else {
        #pragma unroll
        for (int j = 0; j < 8; ++j) {
            const int col = Nbase + wcol + tcol + 4 * j;
            const float bj = bias[col];
            #pragma unroll
            for (int i = 0; i < 8; ++i) {
                const int row = Mbase + wrow + trow + 8 * i;
                out[(size_t)row * OUT_F + col] = fmaf((float)dacc[i][j], s, bj);
            }
        }
    }
}

// ===================== launch =====================
extern "C" void kernel_launch(void* const* d_in, const int* in_sizes, int n_in,
                              void* d_out, int out_size) {
    const float* x    = (const float*)d_in[0];
    const int*   qw   = (const int*)d_in[1];
    const float* ws   = (const float*)d_in[2];
    const float* bias = (const float*)d_in[3];
    float* out = (float*)d_out;

    k_maxabs<<<1024, 256>>>(x);
    k_finalize<<<1, 1024>>>();
    k_prep<<<2048, 256>>>(x, qw);
    cudaFuncSetAttribute(k_gemm, cudaFuncAttributeMaxDynamicSharedMemorySize, SMEM_TOTAL);
    k_gemm<<<dim3(OUT_F / 128, T / 128), 256, SMEM_TOTAL>>>(ws, bias, out);
}

// round 7
// speedup vs baseline: 1.2874x; 1.1257x over previous
#include <cuda_runtime.h>
#include <cuda_bf16.h>
#include <cstdint>

// ===================== problem dims / tiles =====================
static constexpr int T     = 4096;   // tokens (M)
static constexpr int IN_F  = 4096;   // K
static constexpr int OUT_F = 4096;   // N
static constexpr int KC    = 64;     // K chunk bytes (int8)
static constexpr int KITERS = IN_F / KC;   // 64
static constexpr int ROWB  = 80;     // smem row stride (conflict-free ldmatrix + lds32)
static constexpr int STAGES = 4;
static constexpr int SSTR  = 256 * ROWB;             // bytes per stage (A rows 0-127, B rows 128-255)
static constexpr int SMEM_TOTAL = STAGES * SSTR;     // 81920

// ===================== device scratch =====================
__device__ float g_partial[1024];
__device__ float g_scale;
__device__ float g_inv;
__device__ __align__(16) int8_t g_qx[(size_t)T * IN_F];     // 16MB quantized activations
__device__ __align__(16) int8_t g_wt[(size_t)OUT_F * IN_F]; // 16MB int8 weights

// ===================== helpers =====================
__device__ __forceinline__ uint32_t smem_u32(const void* p) {
    uint32_t a;
    asm("{ .reg .u64 t; cvta.to.shared.u64 t, %1; cvt.u32.u64 %0, t; }" : "=r"(a) : "l"(p));
    return a;
}
__device__ __forceinline__ void ldsm_x4(uint32_t* r, uint32_t addr) {
    asm volatile("ldmatrix.sync.aligned.m8n8.x4.shared.b16 {%0,%1,%2,%3}, [%4];"
                 : "=r"(r[0]), "=r"(r[1]), "=r"(r[2]), "=r"(r[3]) : "r"(addr));
}
__device__ __forceinline__ void mma_s8(int* c, const uint32_t* a, const uint32_t* b) {
    asm volatile(
        "mma.sync.aligned.m16n8k32.row.col.s32.s8.s8.s32 "
        "{%0,%1,%2,%3}, {%4,%5,%6,%7}, {%8,%9}, {%0,%1,%2,%3};"
        : "+r"(c[0]), "+r"(c[1]), "+r"(c[2]), "+r"(c[3])
        : "r"(a[0]), "r"(a[1]), "r"(a[2]), "r"(a[3]), "r"(b[0]), "r"(b[1]));
}
__device__ __forceinline__ int lds32(uint32_t addr) {
    int v;
    asm volatile("ld.shared.b32 %0, [%1];" : "=r"(v) : "r"(addr));
    return v;
}
__device__ __forceinline__ void cp16(uint32_t saddr, const void* gaddr) {
    asm volatile("cp.async.cg.shared.global [%0], [%1], 16;" :: "r"(saddr), "l"(gaddr));
}
__device__ __forceinline__ void cp_commit() {
    asm volatile("cp.async.commit_group;" ::: "memory");
}
__device__ __forceinline__ void cp_wait2() {
    asm volatile("cp.async.wait_group 2;" ::: "memory");
}

// ===================== stage 1: max|x| =====================
__global__ void k_maxabs(const float* __restrict__ x) {
    __shared__ float red[256];
    float m = 0.f;
    const float4* x4 = (const float4*)x;
    const int n4 = T * IN_F / 4;
    for (int i = blockIdx.x * blockDim.x + threadIdx.x; i < n4; i += gridDim.x * blockDim.x) {
        float4 v = x4[i];
        m = fmaxf(m, fmaxf(fmaxf(fabsf(v.x), fabsf(v.y)), fmaxf(fabsf(v.z), fabsf(v.w))));
    }
    red[threadIdx.x] = m;
    __syncthreads();
    #pragma unroll
    for (int s = 128; s > 0; s >>= 1) {
        if (threadIdx.x < s) red[threadIdx.x] = fmaxf(red[threadIdx.x], red[threadIdx.x + s]);
        __syncthreads();
    }
    if (threadIdx.x == 0) g_partial[blockIdx.x] = red[0];
}

__global__ void k_finalize() {
    __shared__ float red[1024];
    red[threadIdx.x] = g_partial[threadIdx.x];
    __syncthreads();
    #pragma unroll
    for (int s = 512; s > 0; s >>= 1) {
        if (threadIdx.x < s) red[threadIdx.x] = fmaxf(red[threadIdx.x], red[threadIdx.x + s]);
        __syncthreads();
    }
    if (threadIdx.x == 0) {
        float sc = __fdiv_rn(red[0], 127.0f);
        g_scale = sc;
        g_inv = __fdiv_rn(1.0f, sc);
    }
}

// ===================== stage 2: fused quantize-x + weight-convert =====================
__global__ void k_prep(const float* __restrict__ x, const int* __restrict__ w) {
    const int HALF = 1024;
    const int n4 = T * IN_F / 4;
    if (blockIdx.x < HALF) {
        const float inv = g_inv;
        const float4* x4 = (const float4*)x;
        uint32_t* o = (uint32_t*)g_qx;
        for (int i = blockIdx.x * blockDim.x + threadIdx.x; i < n4; i += HALF * blockDim.x) {
            float4 v = x4[i];
            int q0 = __float2int_rn(v.x * inv);
            int q1 = __float2int_rn(v.y * inv);
            int q2 = __float2int_rn(v.z * inv);
            int q3 = __float2int_rn(v.w * inv);
            o[i] = (q0 & 0xFF) | ((q1 & 0xFF) << 8) | ((q2 & 0xFF) << 16) | ((uint32_t)(q3 & 0xFF) << 24);
        }
    } else {
        const int4* w4 = (const int4*)w;
        uint32_t* o = (uint32_t*)g_wt;
        for (int i = (blockIdx.x - HALF) * blockDim.x + threadIdx.x; i < n4; i += HALF * blockDim.x) {
            int4 v = w4[i];
            o[i] = (v.x & 0xFF) | ((v.y & 0xFF) << 8) | ((v.z & 0xFF) << 16) | ((uint32_t)(v.w & 0xFF) << 24);
        }
    }
}

// ===================== stage 3: per-warp fused tensor+dp4a GEMM =====================
// CTA 128x128, 8 warps, 2 CTAs/SM. Each warp:
//   mma.sync warp tile 32x48 over cols [0,96)   (warp grid 4M x 2N)
//   dp4a    warp tile 16x32 over cols [96,128)  (warp w owns rows [16w,16w+16))
// IMMA is issued first each iter; dp4a streams underneath it on the fma/alu pipe.
__global__ void __launch_bounds__(256, 2) k_gemm(const float* __restrict__ wscale,
                                                 const float* __restrict__ bias,
                                                 float* __restrict__ out) {
    extern __shared__ __align__(16) char smem[];
    const uint32_t sbase = smem_u32(smem);

    const int tid  = threadIdx.x;
    const int lane = tid & 31;
    const int wid  = tid >> 5;
    const int Mbase = blockIdx.y * 128;
    const int Nbase = blockIdx.x * 128;

    // ---- staging (all 256 threads): A rows r0, r0+64; B rows 128+r0, 192+r0 ----
    const int r0 = tid >> 2;             // 0..63
    const int cb = (tid & 3) * 16;       // byte col in 64B chunk
    const int8_t* gA0 = g_qx + (size_t)(Mbase + r0)      * IN_F + cb;
    const int8_t* gA1 = g_qx + (size_t)(Mbase + r0 + 64) * IN_F + cb;
    const int8_t* gB0 = g_wt + (size_t)(Nbase + r0)      * IN_F + cb;
    const int8_t* gB1 = g_wt + (size_t)(Nbase + r0 + 64) * IN_F + cb;
    const uint32_t sA0 = sbase + (uint32_t)r0 * ROWB + cb;
    const uint32_t sA1 = sA0 + 64u * ROWB;
    const uint32_t sB0 = sA0 + 128u * ROWB;
    const uint32_t sB1 = sA0 + 192u * ROWB;

    // ---- mma mapping: warp grid 4(M) x 2(N), warp tile 32x48 ----
    const int mwarp = wid >> 1;          // 0..3 -> rows mwarp*32
    const int nwarp = wid & 1;           // 0..1 -> cols nwarp*48
    const int tile = lane >> 3;
    const int sub  = lane & 7;
    uint32_t aoff[2], boff[3];
    #pragma unroll
    for (int mb = 0; mb < 2; ++mb)
        aoff[mb] = sbase + (uint32_t)(mwarp * 32 + mb * 16 + (tile & 1) * 8 + sub) * ROWB
                 + (uint32_t)(tile >> 1) * 16;
    #pragma unroll
    for (int p = 0; p < 3; ++p)
        boff[p] = sbase + (uint32_t)(128 + nwarp * 48 + p * 16 + (tile >> 1) * 8 + sub) * ROWB
                 + (uint32_t)(tile & 1) * 16;

    // ---- dp4a mapping: warp wid owns A-rows [16*wid, 16*wid+16), cols [96,128) ----
    const int trow = lane >> 3;          // 0..3 -> rows 16*wid + trow + 4i
    const int tcol = lane & 7;           // 0..7 -> cols 96 + tcol + 8j
    const uint32_t dA = sbase + (uint32_t)(wid * 16 + trow) * ROWB;       // +i*4*ROWB
    const uint32_t dB = sbase + (uint32_t)(128 + 96 + tcol) * ROWB;       // +j*8*ROWB

    int acc[2][6][4];                    // mma accumulators (32x48)
    #pragma unroll
    for (int mb = 0; mb < 2; ++mb)
        #pragma unroll
        for (int nb = 0; nb < 6; ++nb)
            #pragma unroll
            for (int f = 0; f < 4; ++f) acc[mb][nb][f] = 0;
    int dacc[4][4];                      // dp4a accumulators (16x32 warp tile)
    #pragma unroll
    for (int i = 0; i < 4; ++i)
        #pragma unroll
        for (int j = 0; j < 4; ++j) dacc[i][j] = 0;

    // prologue: issue stages 0..2
    #pragma unroll
    for (int s = 0; s < STAGES - 1; ++s) {
        const uint32_t so = (uint32_t)s * SSTR;
        const int ko = s * KC;
        cp16(sA0 + so, gA0 + ko);
        cp16(sA1 + so, gA1 + ko);
        cp16(sB0 + so, gB0 + ko);
        cp16(sB1 + so, gB1 + ko);
        cp_commit();
    }

    for (int it = 0; it < KITERS; ++it) {
        cp_wait2();                 // stage it landed
        __syncthreads();            // all warps done with stage it-1

        if (it + STAGES - 1 < KITERS) {
            const uint32_t so = (uint32_t)((it + STAGES - 1) & (STAGES - 1)) * SSTR;
            const int ko = (it + STAGES - 1) * KC;
            cp16(sA0 + so, gA0 + ko);
            cp16(sA1 + so, gA1 + ko);
            cp16(sB0 + so, gB0 + ko);
            cp16(sB1 + so, gB1 + ko);
        }
        cp_commit();

        const uint32_t so = (uint32_t)(it & (STAGES - 1)) * SSTR;

        // ---------- tensor path first: launch IMMAs onto the tensor pipe ----------
        #pragma unroll
        for (int ks = 0; ks < 2; ++ks) {
            uint32_t af[2][4];
            uint32_t bf[6][2];
            #pragma unroll
            for (int mb = 0; mb < 2; ++mb)
                ldsm_x4(af[mb], aoff[mb] + so + ks * 32);
            #pragma unroll
            for (int p = 0; p < 3; ++p) {
                uint32_t r[4];
                ldsm_x4(r, boff[p] + so + ks * 32);
                bf[p * 2 + 0][0] = r[0]; bf[p * 2 + 0][1] = r[1];
                bf[p * 2 + 1][0] = r[2]; bf[p * 2 + 1][1] = r[3];
            }
            #pragma unroll
            for (int mb = 0; mb < 2; ++mb)
                #pragma unroll
                for (int nb = 0; nb < 6; ++nb)
                    mma_s8(acc[mb][nb], af[mb], bf[nb]);
        }

        // ---------- dp4a path: streams on fma/alu pipe while IMMAs drain ----------
        #pragma unroll
        for (int q = 0; q < 16; ++q) {   // 16 x 4-byte K-words per 64B chunk
            int a[4], b[4];
            #pragma unroll
            for (int i = 0; i < 4; ++i)
                a[i] = lds32(dA + so + (uint32_t)i * (4u * ROWB) + (uint32_t)q * 4u);
            #pragma unroll
            for (int j = 0; j < 4; ++j)
                b[j] = lds32(dB + so + (uint32_t)j * (8u * ROWB) + (uint32_t)q * 4u);
            #pragma unroll
            for (int i = 0; i < 4; ++i)
                #pragma unroll
                for (int j = 0; j < 4; ++j)
                    dacc[i][j] = __dp4a(a[i], b[j], dacc[i][j]);
        }
    }

    // ---------- epilogue: exact int32 -> fp32 scale + bias ----------
    const float s = g_scale * wscale[0];
    {   // mma tile: cols [0,96)
        const int g   = lane >> 2;
        const int tg2 = (lane & 3) * 2;
        #pragma unroll
        for (int nb = 0; nb < 6; ++nb) {
            const int col = Nbase + nwarp * 48 + nb * 8 + tg2;
            const float2 bb = *(const float2*)(bias + col);
            #pragma unroll
            for (int mb = 0; mb < 2; ++mb) {
                const int row = Mbase + mwarp * 32 + mb * 16 + g;
                float2 v0, v1;
                v0.x = fmaf((float)acc[mb][nb][0], s, bb.x);
                v0.y = fmaf((float)acc[mb][nb][1], s, bb.y);
                v1.x = fmaf((float)acc[mb][nb][2], s, bb.x);
                v1.y = fmaf((float)acc[mb][nb][3], s, bb.y);
                *(float2*)(out + (size_t)row * OUT_F + col)       = v0;
                *(float2*)(out + (size_t)(row + 8) * OUT_F + col) = v1;
            }
        }
    }
    {   // dp4a tile: cols [96,128)
        #pragma unroll
        for (int j = 0; j < 4; ++j) {
            const int col = Nbase + 96 + tcol + 8 * j;
            const float bj = bias[col];
            #pragma unroll
            for (int i = 0; i < 4; ++i) {
                const int row = Mbase + wid * 16 + trow + 4 * i;
                out[(size_t)row * OUT_F + col] = fmaf((float)dacc[i][j], s, bj);
            }
        }
    }
}

// ===================== launch =====================
extern "C" void kernel_launch(void* const* d_in, const int* in_sizes, int n_in,
                              void* d_out, int out_size) {
    const float* x    = (const float*)d_in[0];
    const int*   qw   = (const int*)d_in[1];
    const float* ws   = (const float*)d_in[2];
    const float* bias = (const float*)d_in[3];
    float* out = (float*)d_out;

    k_maxabs<<<1024, 256>>>(x);
    k_finalize<<<1, 1024>>>();
    k_prep<<<2048, 256>>>(x, qw);
    cudaFuncSetAttribute(k_gemm, cudaFuncAttributeMaxDynamicSharedMemorySize, SMEM_TOTAL);
    k_gemm<<<dim3(OUT_F / 128, T / 128), 256, SMEM_TOTAL>>>(ws, bias, out);
}

// round 8
// speedup vs baseline: 1.2875x; 1.0001x over previous
#include <cuda_runtime.h>
#include <cuda_bf16.h>
#include <cstdint>

// ===================== problem dims / tiles =====================
static constexpr int T     = 4096;   // tokens (M)
static constexpr int IN_F  = 4096;   // K
static constexpr int OUT_F = 4096;   // N
static constexpr int KC    = 64;     // K chunk bytes (int8)
static constexpr int KITERS = IN_F / KC;   // 64
static constexpr int ROWB  = 80;     // smem row stride (conflict-free ldmatrix + lds)
static constexpr int STAGES = 4;
static constexpr int SSTR  = 256 * ROWB;             // bytes per stage (A rows 0-127, B rows 128-255)
static constexpr int SMEM_TOTAL = STAGES * SSTR;     // 81920

// ===================== device scratch =====================
__device__ float g_partial[2048];
__device__ float g_scale;
__device__ float g_inv;
__device__ __align__(16) int8_t g_qx[(size_t)T * IN_F];     // 16MB quantized activations
__device__ __align__(16) int8_t g_wt[(size_t)OUT_F * IN_F]; // 16MB int8 weights

// ===================== helpers =====================
__device__ __forceinline__ uint32_t smem_u32(const void* p) {
    uint32_t a;
    asm("{ .reg .u64 t; cvta.to.shared.u64 t, %1; cvt.u32.u64 %0, t; }" : "=r"(a) : "l"(p));
    return a;
}
__device__ __forceinline__ void ldsm_x4(uint32_t* r, uint32_t addr) {
    asm volatile("ldmatrix.sync.aligned.m8n8.x4.shared.b16 {%0,%1,%2,%3}, [%4];"
                 : "=r"(r[0]), "=r"(r[1]), "=r"(r[2]), "=r"(r[3]) : "r"(addr));
}
__device__ __forceinline__ void mma_s8(int* c, const uint32_t* a, const uint32_t* b) {
    asm volatile(
        "mma.sync.aligned.m16n8k32.row.col.s32.s8.s8.s32 "
        "{%0,%1,%2,%3}, {%4,%5,%6,%7}, {%8,%9}, {%0,%1,%2,%3};"
        : "+r"(c[0]), "+r"(c[1]), "+r"(c[2]), "+r"(c[3])
        : "r"(a[0]), "r"(a[1]), "r"(a[2]), "r"(a[3]), "r"(b[0]), "r"(b[1]));
}
__device__ __forceinline__ void lds64(int& v0, int& v1, uint32_t addr) {
    asm volatile("ld.shared.v2.b32 {%0,%1}, [%2];" : "=r"(v0), "=r"(v1) : "r"(addr));
}
__device__ __forceinline__ void cp16(uint32_t saddr, const void* gaddr) {
    asm volatile("cp.async.cg.shared.global [%0], [%1], 16;" :: "r"(saddr), "l"(gaddr));
}
__device__ __forceinline__ void cp_commit() {
    asm volatile("cp.async.commit_group;" ::: "memory");
}
__device__ __forceinline__ void cp_wait2() {
    asm volatile("cp.async.wait_group 2;" ::: "memory");
}

// ===================== stage 1: max|x| =====================
__global__ void k_maxabs(const float* __restrict__ x) {
    __shared__ float red[256];
    float m = 0.f;
    const float4* x4 = (const float4*)x;
    const int n4 = T * IN_F / 4;
    for (int i = blockIdx.x * blockDim.x + threadIdx.x; i < n4; i += gridDim.x * blockDim.x) {
        float4 v = x4[i];
        m = fmaxf(m, fmaxf(fmaxf(fabsf(v.x), fabsf(v.y)), fmaxf(fabsf(v.z), fabsf(v.w))));
    }
    red[threadIdx.x] = m;
    __syncthreads();
    #pragma unroll
    for (int s = 128; s > 0; s >>= 1) {
        if (threadIdx.x < s) red[threadIdx.x] = fmaxf(red[threadIdx.x], red[threadIdx.x + s]);
        __syncthreads();
    }
    if (threadIdx.x == 0) g_partial[blockIdx.x] = red[0];
}

__global__ void k_finalize() {
    __shared__ float red[1024];
    red[threadIdx.x] = fmaxf(g_partial[threadIdx.x], g_partial[threadIdx.x + 1024]);
    __syncthreads();
    #pragma unroll
    for (int s = 512; s > 0; s >>= 1) {
        if (threadIdx.x < s) red[threadIdx.x] = fmaxf(red[threadIdx.x], red[threadIdx.x + s]);
        __syncthreads();
    }
    if (threadIdx.x == 0) {
        float sc = __fdiv_rn(red[0], 127.0f);
        g_scale = sc;
        g_inv = __fdiv_rn(1.0f, sc);
    }
}

// ===================== stage 2: fused quantize-x + weight-convert =====================
__global__ void k_prep(const float* __restrict__ x, const int* __restrict__ w) {
    const int HALF = 1024;
    const int n4 = T * IN_F / 4;
    if (blockIdx.x < HALF) {
        const float inv = g_inv;
        const float4* x4 = (const float4*)x;
        uint32_t* o = (uint32_t*)g_qx;
        for (int i = blockIdx.x * blockDim.x + threadIdx.x; i < n4; i += HALF * blockDim.x) {
            float4 v = x4[i];
            int q0 = __float2int_rn(v.x * inv);
            int q1 = __float2int_rn(v.y * inv);
            int q2 = __float2int_rn(v.z * inv);
            int q3 = __float2int_rn(v.w * inv);
            o[i] = (q0 & 0xFF) | ((q1 & 0xFF) << 8) | ((q2 & 0xFF) << 16) | ((uint32_t)(q3 & 0xFF) << 24);
        }
    } else {
        const int4* w4 = (const int4*)w;
        uint32_t* o = (uint32_t*)g_wt;
        for (int i = (blockIdx.x - HALF) * blockDim.x + threadIdx.x; i < n4; i += HALF * blockDim.x) {
            int4 v = w4[i];
            o[i] = (v.x & 0xFF) | ((v.y & 0xFF) << 8) | ((v.z & 0xFF) << 16) | ((uint32_t)(v.w & 0xFF) << 24);
        }
    }
}

// ===================== stage 3: per-warp fused tensor+dp4a GEMM =====================
// CTA 128x128, 8 warps, 2 CTAs/SM. Each warp:
//   mma.sync warp tile 32x48 over cols [0,96)   (warp grid 4M x 2N)
//   dp4a    warp tile 16x32 over cols [96,128)  (warp w owns rows [16w,16w+16))
// IMMA issued first each iter; dp4a (v2-vectorized smem loads) streams underneath.
__global__ void __launch_bounds__(256, 2) k_gemm(const float* __restrict__ wscale,
                                                 const float* __restrict__ bias,
                                                 float* __restrict__ out) {
    extern __shared__ __align__(16) char smem[];
    const uint32_t sbase = smem_u32(smem);

    const int tid  = threadIdx.x;
    const int lane = tid & 31;
    const int wid  = tid >> 5;
    const int Mbase = blockIdx.y * 128;
    const int Nbase = blockIdx.x * 128;

    // ---- staging (all 256 threads): A rows r0, r0+64; B rows 128+r0, 192+r0 ----
    const int r0 = tid >> 2;             // 0..63
    const int cb = (tid & 3) * 16;       // byte col in 64B chunk
    const int8_t* gA0 = g_qx + (size_t)(Mbase + r0)      * IN_F + cb;
    const int8_t* gA1 = g_qx + (size_t)(Mbase + r0 + 64) * IN_F + cb;
    const int8_t* gB0 = g_wt + (size_t)(Nbase + r0)      * IN_F + cb;
    const int8_t* gB1 = g_wt + (size_t)(Nbase + r0 + 64) * IN_F + cb;
    const uint32_t sA0 = sbase + (uint32_t)r0 * ROWB + cb;
    const uint32_t sA1 = sA0 + 64u * ROWB;
    const uint32_t sB0 = sA0 + 128u * ROWB;
    const uint32_t sB1 = sA0 + 192u * ROWB;

    // ---- mma mapping: warp grid 4(M) x 2(N), warp tile 32x48 ----
    const int mwarp = wid >> 1;          // 0..3 -> rows mwarp*32
    const int nwarp = wid & 1;           // 0..1 -> cols nwarp*48
    const int tile = lane >> 3;
    const int sub  = lane & 7;
    uint32_t aoff[2], boff[3];
    #pragma unroll
    for (int mb = 0; mb < 2; ++mb)
        aoff[mb] = sbase + (uint32_t)(mwarp * 32 + mb * 16 + (tile & 1) * 8 + sub) * ROWB
                 + (uint32_t)(tile >> 1) * 16;
    #pragma unroll
    for (int p = 0; p < 3; ++p)
        boff[p] = sbase + (uint32_t)(128 + nwarp * 48 + p * 16 + (tile >> 1) * 8 + sub) * ROWB
                 + (uint32_t)(tile & 1) * 16;

    // ---- dp4a mapping: warp wid owns A-rows [16*wid, 16*wid+16), cols [96,128) ----
    const int trow = lane >> 3;          // 0..3 -> rows 16*wid + trow + 4i
    const int tcol = lane & 7;           // 0..7 -> cols 96 + tcol + 8j
    const uint32_t dA = sbase + (uint32_t)(wid * 16 + trow) * ROWB;       // +i*4*ROWB
    const uint32_t dB = sbase + (uint32_t)(128 + 96 + tcol) * ROWB;       // +j*8*ROWB

    int acc[2][6][4];                    // mma accumulators (32x48)
    #pragma unroll
    for (int mb = 0; mb < 2; ++mb)
        #pragma unroll
        for (int nb = 0; nb < 6; ++nb)
            #pragma unroll
            for (int f = 0; f < 4; ++f) acc[mb][nb][f] = 0;
    int dacc[4][4];                      // dp4a accumulators (16x32 warp tile)
    #pragma unroll
    for (int i = 0; i < 4; ++i)
        #pragma unroll
        for (int j = 0; j < 4; ++j) dacc[i][j] = 0;

    // prologue: issue stages 0..2
    #pragma unroll
    for (int s = 0; s < STAGES - 1; ++s) {
        const uint32_t so = (uint32_t)s * SSTR;
        const int ko = s * KC;
        cp16(sA0 + so, gA0 + ko);
        cp16(sA1 + so, gA1 + ko);
        cp16(sB0 + so, gB0 + ko);
        cp16(sB1 + so, gB1 + ko);
        cp_commit();
    }

    for (int it = 0; it < KITERS; ++it) {
        cp_wait2();                 // stage it landed
        __syncthreads();            // all warps done with stage it-1

        if (it + STAGES - 1 < KITERS) {
            const uint32_t so = (uint32_t)((it + STAGES - 1) & (STAGES - 1)) * SSTR;
            const int ko = (it + STAGES - 1) * KC;
            cp16(sA0 + so, gA0 + ko);
            cp16(sA1 + so, gA1 + ko);
            cp16(sB0 + so, gB0 + ko);
            cp16(sB1 + so, gB1 + ko);
        }
        cp_commit();

        const uint32_t so = (uint32_t)(it & (STAGES - 1)) * SSTR;

        // ---------- tensor path first: launch IMMAs onto the tensor pipe ----------
        #pragma unroll
        for (int ks = 0; ks < 2; ++ks) {
            uint32_t af[2][4];
            uint32_t bf[6][2];
            #pragma unroll
            for (int mb = 0; mb < 2; ++mb)
                ldsm_x4(af[mb], aoff[mb] + so + ks * 32);
            #pragma unroll
            for (int p = 0; p < 3; ++p) {
                uint32_t r[4];
                ldsm_x4(r, boff[p] + so + ks * 32);
                bf[p * 2 + 0][0] = r[0]; bf[p * 2 + 0][1] = r[1];
                bf[p * 2 + 1][0] = r[2]; bf[p * 2 + 1][1] = r[3];
            }
            #pragma unroll
            for (int mb = 0; mb < 2; ++mb)
                #pragma unroll
                for (int nb = 0; nb < 6; ++nb)
                    mma_s8(acc[mb][nb], af[mb], bf[nb]);
        }

        // ---------- dp4a path: v2-vectorized loads, streams while IMMAs drain ----------
        #pragma unroll
        for (int qb = 0; qb < 8; ++qb) {   // 8 q-pairs = 16 x 4-byte K-words
            int a0[4], a1[4], b0[4], b1[4];
            #pragma unroll
            for (int i = 0; i < 4; ++i)
                lds64(a0[i], a1[i], dA + so + (uint32_t)i * (4u * ROWB) + (uint32_t)qb * 8u);
            #pragma unroll
            for (int j = 0; j < 4; ++j)
                lds64(b0[j], b1[j], dB + so + (uint32_t)j * (8u * ROWB) + (uint32_t)qb * 8u);
            #pragma unroll
            for (int i = 0; i < 4; ++i)
                #pragma unroll
                for (int j = 0; j < 4; ++j) {
                    dacc[i][j] = __dp4a(a0[i], b0[j], dacc[i][j]);
                    dacc[i][j] = __dp4a(a1[i], b1[j], dacc[i][j]);
                }
        }
    }

    // ---------- epilogue: exact int32 -> fp32 scale + bias ----------
    const float s = g_scale * wscale[0];
    {   // mma tile: cols [0,96)
        const int g   = lane >> 2;
        const int tg2 = (lane & 3) * 2;
        #pragma unroll
        for (int nb = 0; nb < 6; ++nb) {
            const int col = Nbase + nwarp * 48 + nb * 8 + tg2;
            const float2 bb = *(const float2*)(bias + col);
            #pragma unroll
            for (int mb = 0; mb < 2; ++mb) {
                const int row = Mbase + mwarp * 32 + mb * 16 + g;
                float2 v0, v1;
                v0.x = fmaf((float)acc[mb][nb][0], s, bb.x);
                v0.y = fmaf((float)acc[mb][nb][1], s, bb.y);
                v1.x = fmaf((float)acc[mb][nb][2], s, bb.x);
                v1.y = fmaf((float)acc[mb][nb][3], s, bb.y);
                *(float2*)(out + (size_t)row * OUT_F + col)       = v0;
                *(float2*)(out + (size_t)(row + 8) * OUT_F + col) = v1;
            }
        }
    }
    {   // dp4a tile: cols [96,128)
        #pragma unroll
        for (int j = 0; j < 4; ++j) {
            const int col = Nbase + 96 + tcol + 8 * j;
            const float bj = bias[col];
            #pragma unroll
            for (int i = 0; i < 4; ++i) {
                const int row = Mbase + wid * 16 + trow + 4 * i;
                out[(size_t)row * OUT_F + col] = fmaf((float)dacc[i][j], s, bj);
            }
        }
    }
}

// ===================== launch =====================
extern "C" void kernel_launch(void* const* d_in, const int* in_sizes, int n_in,
                              void* d_out, int out_size) {
    const float* x    = (const float*)d_in[0];
    const int*   qw   = (const int*)d_in[1];
    const float* ws   = (const float*)d_in[2];
    const float* bias = (const float*)d_in[3];
    float* out = (float*)d_out;

    k_maxabs<<<2048, 256>>>(x);
    k_finalize<<<1, 1024>>>();
    k_prep<<<2048, 256>>>(x, qw);
    cudaFuncSetAttribute(k_gemm, cudaFuncAttributeMaxDynamicSharedMemorySize, SMEM_TOTAL);
    k_gemm<<<dim3(OUT_F / 128, T / 128), 256, SMEM_TOTAL>>>(ws, bias, out);
}

// round 9
// speedup vs baseline: 1.3123x; 1.0193x over previous
#include <cuda_runtime.h>
#include <cuda_bf16.h>
#include <cstdint>

// ===================== problem dims / tiles =====================
static constexpr int T     = 4096;   // tokens (M)
static constexpr int IN_F  = 4096;   // K
static constexpr int OUT_F = 4096;   // N
static constexpr int KC    = 64;     // K chunk bytes (int8)
static constexpr int KITERS = IN_F / KC;   // 64
static constexpr int ROWB  = 80;     // smem row stride (conflict-free ldmatrix + lds)
static constexpr int STAGES = 4;
static constexpr int SSTR  = 256 * ROWB;             // bytes per stage (A rows 0-127, B rows 128-255)
static constexpr int SMEM_TOTAL = STAGES * SSTR;     // 81920
// N-split: tensor cols [0,88), dp4a cols [88,128)  (rate-balanced 279:128)
static constexpr int NB_MMA = 11;    // 11 x 8 = 88 tensor cols
static constexpr int DPC0   = 88;    // dp4a col base

// ===================== device scratch =====================
__device__ float g_partial[2048];
__device__ float g_scale;
__device__ float g_inv;
__device__ __align__(16) int8_t g_qx[(size_t)T * IN_F];     // 16MB quantized activations
__device__ __align__(16) int8_t g_wt[(size_t)OUT_F * IN_F]; // 16MB int8 weights

// ===================== helpers =====================
__device__ __forceinline__ uint32_t smem_u32(const void* p) {
    uint32_t a;
    asm("{ .reg .u64 t; cvta.to.shared.u64 t, %1; cvt.u32.u64 %0, t; }" : "=r"(a) : "l"(p));
    return a;
}
__device__ __forceinline__ void ldsm_x4(uint32_t* r, uint32_t addr) {
    asm volatile("ldmatrix.sync.aligned.m8n8.x4.shared.b16 {%0,%1,%2,%3}, [%4];"
                 : "=r"(r[0]), "=r"(r[1]), "=r"(r[2]), "=r"(r[3]) : "r"(addr));
}
__device__ __forceinline__ void mma_s8(int* c, const uint32_t* a, const uint32_t* b) {
    asm volatile(
        "mma.sync.aligned.m16n8k32.row.col.s32.s8.s8.s32 "
        "{%0,%1,%2,%3}, {%4,%5,%6,%7}, {%8,%9}, {%0,%1,%2,%3};"
        : "+r"(c[0]), "+r"(c[1]), "+r"(c[2]), "+r"(c[3])
        : "r"(a[0]), "r"(a[1]), "r"(a[2]), "r"(a[3]), "r"(b[0]), "r"(b[1]));
}
__device__ __forceinline__ void lds64(int& v0, int& v1, uint32_t addr) {
    asm volatile("ld.shared.v2.b32 {%0,%1}, [%2];" : "=r"(v0), "=r"(v1) : "r"(addr));
}
__device__ __forceinline__ void cp16(uint32_t saddr, const void* gaddr) {
    asm volatile("cp.async.cg.shared.global [%0], [%1], 16;" :: "r"(saddr), "l"(gaddr));
}
__device__ __forceinline__ void cp_commit() {
    asm volatile("cp.async.commit_group;" ::: "memory");
}
__device__ __forceinline__ void cp_wait2() {
    asm volatile("cp.async.wait_group 2;" ::: "memory");
}

// ===================== stage 1: max|x| =====================
__global__ void k_maxabs(const float* __restrict__ x) {
    __shared__ float red[256];
    float m = 0.f;
    const float4* x4 = (const float4*)x;
    const int n4 = T * IN_F / 4;
    for (int i = blockIdx.x * blockDim.x + threadIdx.x; i < n4; i += gridDim.x * blockDim.x) {
        float4 v = x4[i];
        m = fmaxf(m, fmaxf(fmaxf(fabsf(v.x), fabsf(v.y)), fmaxf(fabsf(v.z), fabsf(v.w))));
    }
    red[threadIdx.x] = m;
    __syncthreads();
    #pragma unroll
    for (int s = 128; s > 0; s >>= 1) {
        if (threadIdx.x < s) red[threadIdx.x] = fmaxf(red[threadIdx.x], red[threadIdx.x + s]);
        __syncthreads();
    }
    if (threadIdx.x == 0) g_partial[blockIdx.x] = red[0];
}

__global__ void k_finalize() {
    __shared__ float red[1024];
    red[threadIdx.x] = fmaxf(g_partial[threadIdx.x], g_partial[threadIdx.x + 1024]);
    __syncthreads();
    #pragma unroll
    for (int s = 512; s > 0; s >>= 1) {
        if (threadIdx.x < s) red[threadIdx.x] = fmaxf(red[threadIdx.x], red[threadIdx.x + s]);
        __syncthreads();
    }
    if (threadIdx.x == 0) {
        float sc = __fdiv_rn(red[0], 127.0f);
        g_scale = sc;
        g_inv = __fdiv_rn(1.0f, sc);
    }
}

// ===================== stage 2: fused quantize-x + weight-convert =====================
__global__ void k_prep(const float* __restrict__ x, const int* __restrict__ w) {
    const int HALF = 1024;
    const int n4 = T * IN_F / 4;
    if (blockIdx.x < HALF) {
        const float inv = g_inv;
        const float4* x4 = (const float4*)x;
        uint32_t* o = (uint32_t*)g_qx;
        for (int i = blockIdx.x * blockDim.x + threadIdx.x; i < n4; i += HALF * blockDim.x) {
            float4 v = x4[i];
            int q0 = __float2int_rn(v.x * inv);
            int q1 = __float2int_rn(v.y * inv);
            int q2 = __float2int_rn(v.z * inv);
            int q3 = __float2int_rn(v.w * inv);
            o[i] = (q0 & 0xFF) | ((q1 & 0xFF) << 8) | ((q2 & 0xFF) << 16) | ((uint32_t)(q3 & 0xFF) << 24);
        }
    } else {
        const int4* w4 = (const int4*)w;
        uint32_t* o = (uint32_t*)g_wt;
        for (int i = (blockIdx.x - HALF) * blockDim.x + threadIdx.x; i < n4; i += HALF * blockDim.x) {
            int4 v = w4[i];
            o[i] = (v.x & 0xFF) | ((v.y & 0xFF) << 8) | ((v.z & 0xFF) << 16) | ((uint32_t)(v.w & 0xFF) << 24);
        }
    }
}

// ===================== stage 3: per-warp fused tensor+dp4a GEMM (88/40 split) =====================
// CTA 128x128, 8 warps (one per 16 M-rows), 2 CTAs/SM. Each warp:
//   mma.sync warp tile 16x88 over cols [0,88)   (11 n-blocks)
//   dp4a    warp tile 16x40 over cols [88,128)  (4x5 per thread)
__global__ void __launch_bounds__(256, 2) k_gemm(const float* __restrict__ wscale,
                                                 const float* __restrict__ bias,
                                                 float* __restrict__ out) {
    extern __shared__ __align__(16) char smem[];
    const uint32_t sbase = smem_u32(smem);

    const int tid  = threadIdx.x;
    const int lane = tid & 31;
    const int wid  = tid >> 5;
    const int Mbase = blockIdx.y * 128;
    const int Nbase = blockIdx.x * 128;

    // ---- staging (all 256 threads): A rows r0, r0+64; B rows 128+r0, 192+r0 ----
    const int r0 = tid >> 2;             // 0..63
    const int cb = (tid & 3) * 16;       // byte col in 64B chunk
    const int8_t* gA0 = g_qx + (size_t)(Mbase + r0)      * IN_F + cb;
    const int8_t* gA1 = g_qx + (size_t)(Mbase + r0 + 64) * IN_F + cb;
    const int8_t* gB0 = g_wt + (size_t)(Nbase + r0)      * IN_F + cb;
    const int8_t* gB1 = g_wt + (size_t)(Nbase + r0 + 64) * IN_F + cb;
    const uint32_t sA0 = sbase + (uint32_t)r0 * ROWB + cb;
    const uint32_t sA1 = sA0 + 64u * ROWB;
    const uint32_t sB0 = sA0 + 128u * ROWB;
    const uint32_t sB1 = sA0 + 192u * ROWB;

    // ---- mma mapping: warp wid owns rows [16*wid, 16*wid+16), cols [0,88) ----
    const int tile = lane >> 3;
    const int sub  = lane & 7;
    const uint32_t aoffw = sbase + (uint32_t)(wid * 16 + (tile & 1) * 8 + sub) * ROWB
                         + (uint32_t)(tile >> 1) * 16;
    uint32_t boff[6];
    #pragma unroll
    for (int p = 0; p < 6; ++p)       // 6 x4-LDSMs cover fragment cols [0,96); MMAs use first 11 blocks
        boff[p] = sbase + (uint32_t)(128 + p * 16 + (tile >> 1) * 8 + sub) * ROWB
                + (uint32_t)(tile & 1) * 16;

    // ---- dp4a mapping: warp wid rows [16*wid,16*wid+16), cols [88,128) ----
    const int trow = lane >> 3;          // 0..3 -> rows 16*wid + trow + 4i
    const int tcol = lane & 7;           // 0..7 -> cols 88 + tcol + 8j (j<5)
    const uint32_t dA = sbase + (uint32_t)(wid * 16 + trow) * ROWB;       // +i*4*ROWB
    const uint32_t dB = sbase + (uint32_t)(128 + DPC0 + tcol) * ROWB;     // +j*8*ROWB

    int acc[NB_MMA][4];                  // mma accumulators (16x88)
    #pragma unroll
    for (int nb = 0; nb < NB_MMA; ++nb)
        #pragma unroll
        for (int f = 0; f < 4; ++f) acc[nb][f] = 0;
    int dacc[4][5];                      // dp4a accumulators (16x40 warp tile)
    #pragma unroll
    for (int i = 0; i < 4; ++i)
        #pragma unroll
        for (int j = 0; j < 5; ++j) dacc[i][j] = 0;

    // prologue: issue stages 0..2
    #pragma unroll
    for (int s = 0; s < STAGES - 1; ++s) {
        const uint32_t so = (uint32_t)s * SSTR;
        const int ko = s * KC;
        cp16(sA0 + so, gA0 + ko);
        cp16(sA1 + so, gA1 + ko);
        cp16(sB0 + so, gB0 + ko);
        cp16(sB1 + so, gB1 + ko);
        cp_commit();
    }

    for (int it = 0; it < KITERS; ++it) {
        cp_wait2();                 // stage it landed
        __syncthreads();            // all warps done with stage it-1

        if (it + STAGES - 1 < KITERS) {
            const uint32_t so = (uint32_t)((it + STAGES - 1) & (STAGES - 1)) * SSTR;
            const int ko = (it + STAGES - 1) * KC;
            cp16(sA0 + so, gA0 + ko);
            cp16(sA1 + so, gA1 + ko);
            cp16(sB0 + so, gB0 + ko);
            cp16(sB1 + so, gB1 + ko);
        }
        cp_commit();

        const uint32_t so = (uint32_t)(it & (STAGES - 1)) * SSTR;

        // ---------- tensor path: fragment loaded per-p and consumed immediately ----------
        #pragma unroll
        for (int ks = 0; ks < 2; ++ks) {
            uint32_t af[4];
            ldsm_x4(af, aoffw + so + ks * 32);
            #pragma unroll
            for (int p = 0; p < 6; ++p) {
                uint32_t r[4];
                ldsm_x4(r, boff[p] + so + ks * 32);
                mma_s8(acc[p * 2], af, r);                 // n-block 2p (always < 11)
                if (p * 2 + 1 < NB_MMA)
                    mma_s8(acc[p * 2 + 1], af, r + 2);     // n-block 2p+1 (skip 12th)
            }
        }

        // ---------- dp4a path: streams on fma/alu pipe while IMMAs drain ----------
        #pragma unroll
        for (int qb = 0; qb < 8; ++qb) {   // 8 q-pairs = 16 x 4-byte K-words
            int a0[4], a1[4], b0[5], b1[5];
            #pragma unroll
            for (int i = 0; i < 4; ++i)
                lds64(a0[i], a1[i], dA + so + (uint32_t)i * (4u * ROWB) + (uint32_t)qb * 8u);
            #pragma unroll
            for (int j = 0; j < 5; ++j)
                lds64(b0[j], b1[j], dB + so + (uint32_t)j * (8u * ROWB) + (uint32_t)qb * 8u);
            #pragma unroll
            for (int i = 0; i < 4; ++i)
                #pragma unroll
                for (int j = 0; j < 5; ++j) {
                    dacc[i][j] = __dp4a(a0[i], b0[j], dacc[i][j]);
                    dacc[i][j] = __dp4a(a1[i], b1[j], dacc[i][j]);
                }
        }
    }

    // ---------- epilogue: exact int32 -> fp32 scale + bias ----------
    const float s = g_scale * wscale[0];
    {   // mma tile: cols [0,88)
        const int g   = lane >> 2;
        const int tg2 = (lane & 3) * 2;
        const int row = Mbase + wid * 16 + g;
        #pragma unroll
        for (int nb = 0; nb < NB_MMA; ++nb) {
            const int col = Nbase + nb * 8 + tg2;
            const float2 bb = *(const float2*)(bias + col);
            float2 v0, v1;
            v0.x = fmaf((float)acc[nb][0], s, bb.x);
            v0.y = fmaf((float)acc[nb][1], s, bb.y);
            v1.x = fmaf((float)acc[nb][2], s, bb.x);
            v1.y = fmaf((float)acc[nb][3], s, bb.y);
            *(float2*)(out + (size_t)row * OUT_F + col)       = v0;
            *(float2*)(out + (size_t)(row + 8) * OUT_F + col) = v1;
        }
    }
    {   // dp4a tile: cols [88,128)
        #pragma unroll
        for (int j = 0; j < 5; ++j) {
            const int col = Nbase + DPC0 + tcol + 8 * j;
            const float bj = bias[col];
            #pragma unroll
            for (int i = 0; i < 4; ++i) {
                const int row = Mbase + wid * 16 + trow + 4 * i;
                out[(size_t)row * OUT_F + col] = fmaf((float)dacc[i][j], s, bj);
            }
        }
    }
}

// ===================== launch =====================
extern "C" void kernel_launch(void* const* d_in, const int* in_sizes, int n_in,
                              void* d_out, int out_size) {
    const float* x    = (const float*)d_in[0];
    const int*   qw   = (const int*)d_in[1];
    const float* ws   = (const float*)d_in[2];
    const float* bias = (const float*)d_in[3];
    float* out = (float*)d_out;

    k_maxabs<<<2048, 256>>>(x);
    k_finalize<<<1, 1024>>>();
    k_prep<<<2048, 256>>>(x, qw);
    cudaFuncSetAttribute(k_gemm, cudaFuncAttributeMaxDynamicSharedMemorySize, SMEM_TOTAL);
    k_gemm<<<dim3(OUT_F / 128, T / 128), 256, SMEM_TOTAL>>>(ws, bias, out);
}

// round 10
// speedup vs baseline: 1.3667x; 1.0414x over previous
#include <cuda_runtime.h>
#include <cuda_bf16.h>
#include <cstdint>

// ===================== problem dims / tiles =====================
static constexpr int T     = 4096;   // tokens (M)
static constexpr int IN_F  = 4096;   // K
static constexpr int OUT_F = 4096;   // N
static constexpr int KC    = 64;     // K chunk bytes (int8)
static constexpr int KITERS = IN_F / KC;   // 64
static constexpr int ROWB  = 80;     // smem row stride (conflict-free ldmatrix + lds)
static constexpr int STAGES = 4;
static constexpr int SSTR  = 256 * ROWB;             // bytes per stage (A rows 0-127, B rows 128-255)
static constexpr int SMEM_TOTAL = STAGES * SSTR;     // 81920
// N-split: tensor cols [0,72), dp4a cols [72,128)
static constexpr int NB_MMA = 9;     // 9 x 8 = 72 tensor cols
static constexpr int DPC0   = 72;    // dp4a col base
static constexpr int DPJ    = 7;     // dp4a col-blocks (7 x 8 = 56 cols)

// ===================== device scratch =====================
__device__ float g_partial[2048];
__device__ float g_scale;
__device__ float g_inv;
__device__ __align__(16) int8_t g_qx[(size_t)T * IN_F];     // 16MB quantized activations
__device__ __align__(16) int8_t g_wt[(size_t)OUT_F * IN_F]; // 16MB int8 weights

// ===================== helpers =====================
__device__ __forceinline__ uint32_t smem_u32(const void* p) {
    uint32_t a;
    asm("{ .reg .u64 t; cvta.to.shared.u64 t, %1; cvt.u32.u64 %0, t; }" : "=r"(a) : "l"(p));
    return a;
}
__device__ __forceinline__ void ldsm_x4(uint32_t* r, uint32_t addr) {
    asm volatile("ldmatrix.sync.aligned.m8n8.x4.shared.b16 {%0,%1,%2,%3}, [%4];"
                 : "=r"(r[0]), "=r"(r[1]), "=r"(r[2]), "=r"(r[3]) : "r"(addr));
}
__device__ __forceinline__ void mma_s8(int* c, const uint32_t* a, const uint32_t* b) {
    asm volatile(
        "mma.sync.aligned.m16n8k32.row.col.s32.s8.s8.s32 "
        "{%0,%1,%2,%3}, {%4,%5,%6,%7}, {%8,%9}, {%0,%1,%2,%3};"
        : "+r"(c[0]), "+r"(c[1]), "+r"(c[2]), "+r"(c[3])
        : "r"(a[0]), "r"(a[1]), "r"(a[2]), "r"(a[3]), "r"(b[0]), "r"(b[1]));
}
__device__ __forceinline__ void lds64(int& v0, int& v1, uint32_t addr) {
    asm volatile("ld.shared.v2.b32 {%0,%1}, [%2];" : "=r"(v0), "=r"(v1) : "r"(addr));
}
__device__ __forceinline__ void cp16(uint32_t saddr, const void* gaddr) {
    asm volatile("cp.async.cg.shared.global [%0], [%1], 16;" :: "r"(saddr), "l"(gaddr));
}
__device__ __forceinline__ void cp_commit() {
    asm volatile("cp.async.commit_group;" ::: "memory");
}
__device__ __forceinline__ void cp_wait2() {
    asm volatile("cp.async.wait_group 2;" ::: "memory");
}

// ===================== stage 1: max|x| =====================
__global__ void k_maxabs(const float* __restrict__ x) {
    __shared__ float red[256];
    float m = 0.f;
    const float4* x4 = (const float4*)x;
    const int n4 = T * IN_F / 4;
    for (int i = blockIdx.x * blockDim.x + threadIdx.x; i < n4; i += gridDim.x * blockDim.x) {
        float4 v = x4[i];
        m = fmaxf(m, fmaxf(fmaxf(fabsf(v.x), fabsf(v.y)), fmaxf(fabsf(v.z), fabsf(v.w))));
    }
    red[threadIdx.x] = m;
    __syncthreads();
    #pragma unroll
    for (int s = 128; s > 0; s >>= 1) {
        if (threadIdx.x < s) red[threadIdx.x] = fmaxf(red[threadIdx.x], red[threadIdx.x + s]);
        __syncthreads();
    }
    if (threadIdx.x == 0) g_partial[blockIdx.x] = red[0];
}

__global__ void k_finalize() {
    __shared__ float red[1024];
    red[threadIdx.x] = fmaxf(g_partial[threadIdx.x], g_partial[threadIdx.x + 1024]);
    __syncthreads();
    #pragma unroll
    for (int s = 512; s > 0; s >>= 1) {
        if (threadIdx.x < s) red[threadIdx.x] = fmaxf(red[threadIdx.x], red[threadIdx.x + s]);
        __syncthreads();
    }
    if (threadIdx.x == 0) {
        float sc = __fdiv_rn(red[0], 127.0f);
        g_scale = sc;
        g_inv = __fdiv_rn(1.0f, sc);
    }
}

// ===================== stage 2: fused quantize-x + weight-convert =====================
__global__ void k_prep(const float* __restrict__ x, const int* __restrict__ w) {
    const int HALF = 1024;
    const int n4 = T * IN_F / 4;
    if (blockIdx.x < HALF) {
        const float inv = g_inv;
        const float4* x4 = (const float4*)x;
        uint32_t* o = (uint32_t*)g_qx;
        for (int i = blockIdx.x * blockDim.x + threadIdx.x; i < n4; i += HALF * blockDim.x) {
            float4 v = x4[i];
            int q0 = __float2int_rn(v.x * inv);
            int q1 = __float2int_rn(v.y * inv);
            int q2 = __float2int_rn(v.z * inv);
            int q3 = __float2int_rn(v.w * inv);
            o[i] = (q0 & 0xFF) | ((q1 & 0xFF) << 8) | ((q2 & 0xFF) << 16) | ((uint32_t)(q3 & 0xFF) << 24);
        }
    } else {
        const int4* w4 = (const int4*)w;
        uint32_t* o = (uint32_t*)g_wt;
        for (int i = (blockIdx.x - HALF) * blockDim.x + threadIdx.x; i < n4; i += HALF * blockDim.x) {
            int4 v = w4[i];
            o[i] = (v.x & 0xFF) | ((v.y & 0xFF) << 8) | ((v.z & 0xFF) << 16) | ((uint32_t)(v.w & 0xFF) << 24);
        }
    }
}

// ===================== stage 3: per-warp fused tensor+dp4a GEMM (72/56 split) =====================
// CTA 128x128, 8 warps (one per 16 M-rows), 2 CTAs/SM. Each warp:
//   mma.sync warp tile 16x72 over cols [0,72)   (9 n-blocks)
//   dp4a    warp tile 16x56 over cols [72,128)  (4x7 per thread)
__global__ void __launch_bounds__(256, 2) k_gemm(const float* __restrict__ wscale,
                                                 const float* __restrict__ bias,
                                                 float* __restrict__ out) {
    extern __shared__ __align__(16) char smem[];
    const uint32_t sbase = smem_u32(smem);

    const int tid  = threadIdx.x;
    const int lane = tid & 31;
    const int wid  = tid >> 5;
    const int Mbase = blockIdx.y * 128;
    const int Nbase = blockIdx.x * 128;

    // ---- staging (all 256 threads): A rows r0, r0+64; B rows 128+r0, 192+r0 ----
    const int r0 = tid >> 2;             // 0..63
    const int cb = (tid & 3) * 16;       // byte col in 64B chunk
    const int8_t* gA0 = g_qx + (size_t)(Mbase + r0)      * IN_F + cb;
    const int8_t* gA1 = g_qx + (size_t)(Mbase + r0 + 64) * IN_F + cb;
    const int8_t* gB0 = g_wt + (size_t)(Nbase + r0)      * IN_F + cb;
    const int8_t* gB1 = g_wt + (size_t)(Nbase + r0 + 64) * IN_F + cb;
    const uint32_t sA0 = sbase + (uint32_t)r0 * ROWB + cb;
    const uint32_t sA1 = sA0 + 64u * ROWB;
    const uint32_t sB0 = sA0 + 128u * ROWB;
    const uint32_t sB1 = sA0 + 192u * ROWB;

    // ---- mma mapping: warp wid owns rows [16*wid, 16*wid+16), cols [0,72) ----
    const int tile = lane >> 3;
    const int sub  = lane & 7;
    const uint32_t aoffw = sbase + (uint32_t)(wid * 16 + (tile & 1) * 8 + sub) * ROWB
                         + (uint32_t)(tile >> 1) * 16;
    uint32_t boff[5];
    #pragma unroll
    for (int p = 0; p < 5; ++p)       // 5 x4-LDSMs cover fragment cols [0,80); MMAs use first 9 blocks
        boff[p] = sbase + (uint32_t)(128 + p * 16 + (tile >> 1) * 8 + sub) * ROWB
                + (uint32_t)(tile & 1) * 16;

    // ---- dp4a mapping: warp wid rows [16*wid,16*wid+16), cols [72,128) ----
    const int trow = lane >> 3;          // 0..3 -> rows 16*wid + trow + 4i
    const int tcol = lane & 7;           // 0..7 -> cols 72 + tcol + 8j (j<7)
    const uint32_t dA = sbase + (uint32_t)(wid * 16 + trow) * ROWB;       // +i*4*ROWB
    const uint32_t dB = sbase + (uint32_t)(128 + DPC0 + tcol) * ROWB;     // +j*8*ROWB

    int acc[NB_MMA][4];                  // mma accumulators (16x72)
    #pragma unroll
    for (int nb = 0; nb < NB_MMA; ++nb)
        #pragma unroll
        for (int f = 0; f < 4; ++f) acc[nb][f] = 0;
    int dacc[4][DPJ];                    // dp4a accumulators (16x56 warp tile)
    #pragma unroll
    for (int i = 0; i < 4; ++i)
        #pragma unroll
        for (int j = 0; j < DPJ; ++j) dacc[i][j] = 0;

    // prologue: issue stages 0..2
    #pragma unroll
    for (int s = 0; s < STAGES - 1; ++s) {
        const uint32_t so = (uint32_t)s * SSTR;
        const int ko = s * KC;
        cp16(sA0 + so, gA0 + ko);
        cp16(sA1 + so, gA1 + ko);
        cp16(sB0 + so, gB0 + ko);
        cp16(sB1 + so, gB1 + ko);
        cp_commit();
    }

    for (int it = 0; it < KITERS; ++it) {
        cp_wait2();                 // stage it landed
        __syncthreads();            // all warps done with stage it-1

        if (it + STAGES - 1 < KITERS) {
            const uint32_t so = (uint32_t)((it + STAGES - 1) & (STAGES - 1)) * SSTR;
            const int ko = (it + STAGES - 1) * KC;
            cp16(sA0 + so, gA0 + ko);
            cp16(sA1 + so, gA1 + ko);
            cp16(sB0 + so, gB0 + ko);
            cp16(sB1 + so, gB1 + ko);
        }
        cp_commit();

        const uint32_t so = (uint32_t)(it & (STAGES - 1)) * SSTR;

        // ---------- tensor path: fragments loaded per-p, consumed immediately ----------
        #pragma unroll
        for (int ks = 0; ks < 2; ++ks) {
            uint32_t af[4];
            ldsm_x4(af, aoffw + so + ks * 32);
            #pragma unroll
            for (int p = 0; p < 5; ++p) {
                uint32_t r[4];
                ldsm_x4(r, boff[p] + so + ks * 32);
                mma_s8(acc[p * 2], af, r);                 // n-block 2p (always < 9)
                if (p * 2 + 1 < NB_MMA)
                    mma_s8(acc[p * 2 + 1], af, r + 2);     // n-block 2p+1 (skip 10th)
            }
        }

        // ---------- dp4a path: streams on fma/alu pipe while IMMAs drain ----------
        #pragma unroll
        for (int qb = 0; qb < 8; ++qb) {   // 8 q-pairs = 16 x 4-byte K-words
            int a0[4], a1[4], b0[DPJ], b1[DPJ];
            #pragma unroll
            for (int i = 0; i < 4; ++i)
                lds64(a0[i], a1[i], dA + so + (uint32_t)i * (4u * ROWB) + (uint32_t)qb * 8u);
            #pragma unroll
            for (int j = 0; j < DPJ; ++j)
                lds64(b0[j], b1[j], dB + so + (uint32_t)j * (8u * ROWB) + (uint32_t)qb * 8u);
            #pragma unroll
            for (int i = 0; i < 4; ++i)
                #pragma unroll
                for (int j = 0; j < DPJ; ++j) {
                    dacc[i][j] = __dp4a(a0[i], b0[j], dacc[i][j]);
                    dacc[i][j] = __dp4a(a1[i], b1[j], dacc[i][j]);
                }
        }
    }

    // ---------- epilogue: exact int32 -> fp32 scale + bias ----------
    const float s = g_scale * wscale[0];
    {   // mma tile: cols [0,72)
        const int g   = lane >> 2;
        const int tg2 = (lane & 3) * 2;
        const int row = Mbase + wid * 16 + g;
        #pragma unroll
        for (int nb = 0; nb < NB_MMA; ++nb) {
            const int col = Nbase + nb * 8 + tg2;
            const float2 bb = *(const float2*)(bias + col);
            float2 v0, v1;
            v0.x = fmaf((float)acc[nb][0], s, bb.x);
            v0.y = fmaf((float)acc[nb][1], s, bb.y);
            v1.x = fmaf((float)acc[nb][2], s, bb.x);
            v1.y = fmaf((float)acc[nb][3], s, bb.y);
            *(float2*)(out + (size_t)row * OUT_F + col)       = v0;
            *(float2*)(out + (size_t)(row + 8) * OUT_F + col) = v1;
        }
    }
    {   // dp4a tile: cols [72,128)
        #pragma unroll
        for (int j = 0; j < DPJ; ++j) {
            const int col = Nbase + DPC0 + tcol + 8 * j;
            const float bj = bias[col];
            #pragma unroll
            for (int i = 0; i < 4; ++i) {
                const int row = Mbase + wid * 16 + trow + 4 * i;
                out[(size_t)row * OUT_F + col] = fmaf((float)dacc[i][j], s, bj);
            }
        }
    }
}

// ===================== launch =====================
extern "C" void kernel_launch(void* const* d_in, const int* in_sizes, int n_in,
                              void* d_out, int out_size) {
    const float* x    = (const float*)d_in[0];
    const int*   qw   = (const int*)d_in[1];
    const float* ws   = (const float*)d_in[2];
    const float* bias = (const float*)d_in[3];
    float* out = (float*)d_out;

    k_maxabs<<<2048, 256>>>(x);
    k_finalize<<<1, 1024>>>();
    k_prep<<<2048, 256>>>(x, qw);
    cudaFuncSetAttribute(k_gemm, cudaFuncAttributeMaxDynamicSharedMemorySize, SMEM_TOTAL);
    k_gemm<<<dim3(OUT_F / 128, T / 128), 256, SMEM_TOTAL>>>(ws, bias, out);
}